// round 16
// baseline (speedup 1.0000x reference)
#include <cuda_runtime.h>
#include <cuda_fp16.h>

// DWHT (buggy torch in-place semantics) + channel shuffle, fully fused.
// x: (64, 256, 28, 28) f32  ->  out: (64, 512, 28, 28) f32
//
// 8 passes = (F o F)^4; G = F o F maps each aligned 16-channel chunk to a
// fixed signed output set. Channel shuffle (groups=8) folded into affine
// stage-4 addresses.
//
// Round-15 = R11 core (fp16 exchange smem / fp32 compute, quad-packed,
// zero-pad sparsity, CSE butterfly, warp = 32 pixels x 1 chunk-pair) +
//   * cp.async (LDGSTS) input staging: stage-1's 16-LDG front batch (the
//     cross-CTA L1tex-queue contention source) replaced by async copies into
//     a 32KB fp32 staging buffer, read back via conflict-free LDS.
//   * 2 tiles per block (grid 800, deterministic): tile B's copy issues
//     right after tile A's stage-1 barrier and hides under stages 2-4.

#define NPIX   32
#define NTILES (64 * 25)
#define STAGE_WORDS (256 * 32)          // fp32 staging: 256 ch x 32 px = 32KB
#define EXCH_OFF    STAGE_WORDS         // half-exchange starts after staging

// ---- cp.async helpers ----
__device__ __forceinline__ unsigned smem_u32(const void* p) {
    unsigned a;
    asm("{ .reg .u64 t; cvta.to.shared.u64 t, %1; cvt.u32.u64 %0, t; }"
        : "=r"(a) : "l"(p));
    return a;
}
__device__ __forceinline__ void cp_async16(unsigned dst, const void* src) {
    asm volatile("cp.async.cg.shared.global [%0], [%1], 16;"
                 :: "r"(dst), "l"(src));
}
__device__ __forceinline__ void cp_commit() {
    asm volatile("cp.async.commit_group;");
}
__device__ __forceinline__ void cp_wait0() {
    asm volatile("cp.async.wait_group 0;");
}

struct GOut {
    float4 Al;              // -> 4*jl + q
    float2 Bl, Dl, Gl;      // -> 128+2jl, 256+2jl, 384+2jl
    float  El;              // -> 320+jl
    float4 Ah, Ch, G4h;     // -> 4*jh+q, 128+4jh+q, 384+4jh+q
    float2 Bh, Dh, G2h, Fh; // -> 128+2jh, 256+2jh, 384+2jh, 320+2jh
    float  Eh;              // -> 320+jh
};

// CSE'd butterfly.
__device__ __forceinline__ GOut compute_G(const float wl[16], const float wh[16]) {
    GOut o;
    float s[8], t[4], u[4];
#pragma unroll
    for (int i = 0; i < 8; i++) s[i] = wl[2*i] + wl[2*i+1];
#pragma unroll
    for (int q = 0; q < 4; q++) { t[q] = s[2*q] + s[2*q+1]; u[q] = s[2*q] - s[2*q+1]; }
    o.Al = make_float4(t[0], t[1], t[2], t[3]);
    o.Bl = make_float2(u[0] + u[1], u[2] + u[3]);
    o.Dl = make_float2(t[0] - t[1], t[2] - t[3]);
    o.Gl = make_float2(u[0] - u[1], u[2] - u[3]);
    o.El = o.Bl.x - o.Bl.y;

    float d[8];
#pragma unroll
    for (int i = 0; i < 8; i++) { s[i] = wh[2*i] + wh[2*i+1]; d[i] = wh[2*i] - wh[2*i+1]; }
#pragma unroll
    for (int q = 0; q < 4; q++) { t[q] = s[2*q] + s[2*q+1]; u[q] = s[2*q] - s[2*q+1]; }
    o.Ah  = make_float4(t[0], t[1], t[2], t[3]);
    o.Bh  = make_float2(u[0] + u[1], u[2] + u[3]);
    o.Dh  = make_float2(t[0] - t[1], t[2] - t[3]);
    o.G2h = make_float2(u[0] - u[1], u[2] - u[3]);
    o.Eh  = o.Bh.x - o.Bh.y;
    float c0 = d[0]+d[1], c1 = d[2]+d[3], c2 = d[4]+d[5], c3 = d[6]+d[7];
    o.Ch  = make_float4(c0, c1, c2, c3);
    o.G4h = make_float4(d[0]-d[1], d[2]-d[3], d[4]-d[5], d[6]-d[7]);
    o.Fh  = make_float2(c0 - c1, c2 - c3);
    return o;
}

__device__ __forceinline__ void zero16(float w[16]) {
#pragma unroll
    for (int m = 0; m < 16; m++) w[m] = 0.0f;
}

// Quad-packed half layout, addresses in HALVES: sidx(c,p)=(c>>2)*128+4p+(c&3)
__device__ __forceinline__ void load_chunk(const __half* __restrict__ s, int chunk,
                                           int p, float w[16]) {
#pragma unroll
    for (int i = 0; i < 4; i++) {
        uint2 raw = *(const uint2*)(s + (4 * chunk + i) * 128 + 4 * p);
        float2 a = __half22float2(*(__half2*)&raw.x);
        float2 b = __half22float2(*(__half2*)&raw.y);
        w[4*i+0] = a.x; w[4*i+1] = a.y; w[4*i+2] = b.x; w[4*i+3] = b.y;
    }
}
__device__ __forceinline__ void sts4(__half* __restrict__ s, int c, int p, float4 v) {
    __half2 lo = __floats2half2_rn(v.x, v.y);
    __half2 hi = __floats2half2_rn(v.z, v.w);
    uint2 raw; raw.x = *(unsigned*)&lo; raw.y = *(unsigned*)&hi;
    *(uint2*)(s + (c >> 2) * 128 + 4 * p) = raw;
}
__device__ __forceinline__ void sts2(__half* __restrict__ s, int c, int p, float2 v) {
    *(__half2*)(s + (c >> 2) * 128 + 4 * p + (c & 3)) = __floats2half2_rn(v.x, v.y);
}
__device__ __forceinline__ void sts1(__half* __restrict__ s, int c, int p, float v) {
    s[(c >> 2) * 128 + 4 * p + (c & 3)] = __float2half_rn(v);
}

__device__ __forceinline__ void store_G(__half* __restrict__ s, int jl, int p,
                                        const GOut& o, bool skipAl, bool skipH4) {
    const int jh = jl + 16;
    if (!skipAl) sts4(s, 4*jl, p, o.Al);
    sts2(s, 128 + 2*jl, p, o.Bl);
    sts2(s, 256 + 2*jl, p, o.Dl);
    sts2(s, 384 + 2*jl, p, o.Gl);
    sts1(s, 320 + jl, p, o.El);
    if (!skipH4) {
        sts4(s, 4*jh,       p, o.Ah);
        sts4(s, 128 + 4*jh, p, o.Ch);
        sts4(s, 384 + 4*jh, p, o.G4h);
    }
    sts2(s, 128 + 2*jh, p, o.Bh);
    sts2(s, 256 + 2*jh, p, o.Dh);
    sts2(s, 384 + 2*jh, p, o.G2h);
    sts2(s, 320 + 2*jh, p, o.Fh);
    sts1(s, 320 + jh, p, o.Eh);
}

// Async-copy one tile's input (256 ch x 32 px fp32) into staging.
// 2048 16B segments / 512 threads = 4 per thread; fully coalesced.
__device__ __forceinline__ void copy_tile(const float* __restrict__ x, int tile,
                                          unsigned stage_addr, int tid) {
    const int b       = tile / 25;
    const int base_hw = (tile - b * 25) * NPIX;
    const float* src0 = x + (size_t)b * (256 * 784) + base_hw;
    const int seg = tid & 7;                 // 4-pixel segment within row
    const int r0  = tid >> 3;                // row within 64-row group
    // last tile of an image (base_hw=768): segments >=4 would read OOB of the
    // final channel; redirect to a safe dummy (data masked at stage-4 store).
    const bool seg_ok = (base_hw + seg * 4) < 784;
#pragma unroll
    for (int g = 0; g < 4; g++) {
        const int row = g * 64 + r0;         // channel [0,256)
        const float* src = seg_ok ? (src0 + row * 784 + seg * 4) : x;
        cp_async16(stage_addr + (unsigned)(row * 32 + seg * 4) * 4u, src);
    }
    cp_commit();
}

__global__ __launch_bounds__(512, 3)
void dwht_kernel(const float* __restrict__ x, float* __restrict__ out) {
    extern __shared__ float sm[];            // [0,8192) staging fp32 (32KB)
    float*  stage = sm;                      // then 16384 halves (32KB)
    __half* exch  = (__half*)(sm + EXCH_OFF);
    const unsigned stage_addr = smem_u32(stage);

    const int tid = threadIdx.x;
    const int p   = tid & (NPIX - 1);        // pixel lane within warp [0,32)
    const int jl  = tid >> 5;                // chunk pair id = warp id [0,16)
    const int jh  = jl + 16;

    // sparsity predicates (warp-uniform)
    const bool rl2 = (jl <= 3) | (jl == 8) | (jl == 9);
    const bool rh2 = (jl <= 1) | (jl == 4) | (jl == 8) | (jl == 9);
    const bool skipAl = ((jl >= 4) & (jl <= 7)) | (jl >= 12);
    const bool skipH4 = (jl >= 12);
    const bool rl3 = !((jl == 1) | (jl == 3) | (jl == 7) | (jl == 15));
    const bool rh3 = (jl != 15);

    const int t0 = blockIdx.x * 2;           // this block's two tiles
    copy_tile(x, t0, stage_addr, tid);       // tile 0 copy in flight

    float wl[16], wh[16];

#pragma unroll
    for (int it = 0; it < 2; it++) {
        const int tile = t0 + it;
        const int b    = tile / 25;
        const int hw   = (tile - b * 25) * NPIX + p;
        const bool valid = (hw < 784);
        float* op = out + (size_t)b * (512 * 784) + hw;

        cp_wait0();
        __syncthreads();                     // S: staging ready for all

        // ---- stage 1: staging (conflict-free LDS) -> exchange ----
        {
#pragma unroll
            for (int m = 0; m < 16; m++) wl[m] = stage[(16 * jl + m) * 32 + p];
            zero16(wh);
            GOut o = compute_G(wl, wh);      // high outputs fold to 0, DCE'd
            sts4(exch, 4*jl, p, o.Al);
            sts2(exch, 128 + 2*jl, p, o.Bl);
            sts2(exch, 256 + 2*jl, p, o.Dl);
            sts2(exch, 384 + 2*jl, p, o.Gl);
            sts1(exch, 320 + jl, p, o.El);
        }
        __syncthreads();                     // A: staging reads + exch stores done

        // prefetch next tile NOW; hides under stages 2-4
        if (it == 0) copy_tile(x, t0 + 1, stage_addr, tid);

        // ---- stage 2 ----
        {
            if (rl2) load_chunk(exch, jl, p, wl); else zero16(wl);
            if (rh2) load_chunk(exch, jh, p, wh); else zero16(wh);
            GOut o = compute_G(wl, wh);
            __syncthreads();                 // B
            store_G(exch, jl, p, o, skipAl, skipH4);
            __syncthreads();                 // C
        }
        // ---- stage 3 ----
        {
            if (rl3) load_chunk(exch, jl, p, wl); else zero16(wl);
            if (rh3) load_chunk(exch, jh, p, wh); else zero16(wh);
            GOut o = compute_G(wl, wh);
            __syncthreads();                 // D
            store_G(exch, jl, p, o, false, false);
            __syncthreads();                 // E
        }
        // ---- stage 4: exchange -> shuffled global store (affine) ----
        {
            load_chunk(exch, jl, p, wl);
            load_chunk(exch, jh, p, wh);
            GOut o = compute_G(wl, wh);
            if (valid) {
                float* q32  = op + (size_t)(32 * jl) * 784;
                float* q16  = op + (size_t)(16 * jl) * 784;
                float* q16h = q16 + (size_t)256 * 784;
                float* qE   = op + (size_t)(8 * jl) * 784;
                q32[(size_t)( 0*8+0)*784] = o.Al.x;
                q32[(size_t)( 1*8+0)*784] = o.Al.y;
                q32[(size_t)( 2*8+0)*784] = o.Al.z;
                q32[(size_t)( 3*8+0)*784] = o.Al.w;
                q32[(size_t)( 0*8+1)*784] = o.Ah.x;
                q32[(size_t)( 1*8+1)*784] = o.Ah.y;
                q32[(size_t)( 2*8+1)*784] = o.Ah.z;
                q32[(size_t)( 3*8+1)*784] = o.Ah.w;
                q32[(size_t)( 0*8+3)*784] = o.Ch.x;
                q32[(size_t)( 1*8+3)*784] = o.Ch.y;
                q32[(size_t)( 2*8+3)*784] = o.Ch.z;
                q32[(size_t)( 3*8+3)*784] = o.Ch.w;
                q32[(size_t)( 0*8+7)*784] = o.G4h.x;
                q32[(size_t)( 1*8+7)*784] = o.G4h.y;
                q32[(size_t)( 2*8+7)*784] = o.G4h.z;
                q32[(size_t)( 3*8+7)*784] = o.G4h.w;
                q16[(size_t)(0*8+2)*784] = o.Bl.x;
                q16[(size_t)(1*8+2)*784] = o.Bl.y;
                q16[(size_t)(0*8+4)*784] = o.Dl.x;
                q16[(size_t)(1*8+4)*784] = o.Dl.y;
                q16[(size_t)(0*8+6)*784] = o.Gl.x;
                q16[(size_t)(1*8+6)*784] = o.Gl.y;
                q16h[(size_t)(0*8+2)*784] = o.Bh.x;
                q16h[(size_t)(1*8+2)*784] = o.Bh.y;
                q16h[(size_t)(0*8+4)*784] = o.Dh.x;
                q16h[(size_t)(1*8+4)*784] = o.Dh.y;
                q16h[(size_t)(0*8+5)*784] = o.Fh.x;
                q16h[(size_t)(1*8+5)*784] = o.Fh.y;
                q16h[(size_t)(0*8+6)*784] = o.G2h.x;
                q16h[(size_t)(1*8+6)*784] = o.G2h.y;
                qE[(size_t)  5*784] = o.El;
                qE[(size_t)133*784] = o.Eh;
            }
        }
        __syncthreads();                     // F: exchange reuse safe
    }
}

extern "C" void kernel_launch(void* const* d_in, const int* in_sizes, int n_in,
                              void* d_out, int out_size) {
    const float* x = (const float*)d_in[0];
    float* out = (float*)d_out;
    const int smem = STAGE_WORDS * 4 + 128 * 128 * 2;   // 32KB + 32KB = 64KB
    static bool attr_set = false;                        // idempotent
    if (!attr_set) {
        cudaFuncSetAttribute(dwht_kernel,
                             cudaFuncAttributeMaxDynamicSharedMemorySize, smem);
        attr_set = true;
    }
    // 800 blocks x 2 tiles each = 1600 tiles (64 images x 25 tiles)
    dwht_kernel<<<NTILES / 2, 512, smem>>>(x, out);
}

// round 17
// speedup vs baseline: 1.1646x; 1.1646x over previous
#include <cuda_runtime.h>
#include <cuda_fp16.h>

// DWHT (buggy torch in-place semantics) + channel shuffle, fully fused.
// x: (64, 256, 28, 28) f32  ->  out: (64, 512, 28, 28) f32
//
// 8 passes = (F o F)^4; G = F o F maps each aligned 16-channel chunk to a
// fixed signed output set. Channel shuffle (groups=8) folded into affine
// stage-4 addresses.
//
// Round-16: HALF2 SIMD over PIXEL PAIRS. Each thread owns 2 adjacent pixels
// packed in __half2; every butterfly add (HADD2/HSUB2), every LDS/STS, and
// every LDG.64/STG.64 serves 2 pixels per instruction (~45% fewer issue
// slots per pixel; crossbar bytes unchanged -> attacks the measured
// issue/latency bind). Stage 1 computed in fp32 (1 quantization), stages
// 2-4 in fp16 (est. total rel_err ~6e-4 < 1e-3). Pair-packed layout
// idx(c,pp) = (c>>1)*64 + 2pp + (c&1): all accesses conflict-free (R9 math).
// Zero-pad sparsity + CSE butterfly unchanged.

#define NPP 32             // pixel pairs per block -> 64 pixels
#define PAIRS_PER_IMG 392  // 784 / 2

// ---- fp32 low-chunk butterfly for stage 1 ----
struct LowF { float Al[4]; float Bl[2], Dl[2], Gl[2]; float El; };

__device__ __forceinline__ LowF lowG_f(const float w[16]) {
    LowF o; float s[8], t[4], u[4];
#pragma unroll
    for (int i = 0; i < 8; i++) s[i] = w[2*i] + w[2*i+1];
#pragma unroll
    for (int q = 0; q < 4; q++) { t[q] = s[2*q] + s[2*q+1]; u[q] = s[2*q] - s[2*q+1]; }
#pragma unroll
    for (int q = 0; q < 4; q++) o.Al[q] = t[q];
    o.Bl[0] = u[0] + u[1]; o.Bl[1] = u[2] + u[3];
    o.Dl[0] = t[0] - t[1]; o.Dl[1] = t[2] - t[3];
    o.Gl[0] = u[0] - u[1]; o.Gl[1] = u[2] - u[3];
    o.El = o.Bl[0] - o.Bl[1];
    return o;
}

// ---- half2 butterfly (2 pixels per op) ----
struct GH {
    __half2 Al[4];
    __half2 Bl[2], Dl[2], Gl[2];
    __half2 El;
    __half2 Ah[4], Ch[4], G4[4];
    __half2 Bh[2], Dh[2], G2[2], Fh[2];
    __half2 Eh;
};

__device__ __forceinline__ GH compute_GH(const __half2 wl[16], const __half2 wh[16]) {
    GH o;
    __half2 s[8], t[4], u[4];
#pragma unroll
    for (int i = 0; i < 8; i++) s[i] = __hadd2(wl[2*i], wl[2*i+1]);
#pragma unroll
    for (int q = 0; q < 4; q++) { t[q] = __hadd2(s[2*q], s[2*q+1]); u[q] = __hsub2(s[2*q], s[2*q+1]); }
#pragma unroll
    for (int q = 0; q < 4; q++) o.Al[q] = t[q];
    o.Bl[0] = __hadd2(u[0], u[1]); o.Bl[1] = __hadd2(u[2], u[3]);
    o.Dl[0] = __hsub2(t[0], t[1]); o.Dl[1] = __hsub2(t[2], t[3]);
    o.Gl[0] = __hsub2(u[0], u[1]); o.Gl[1] = __hsub2(u[2], u[3]);
    o.El = __hsub2(o.Bl[0], o.Bl[1]);

    __half2 d[8], c[4];
#pragma unroll
    for (int i = 0; i < 8; i++) { s[i] = __hadd2(wh[2*i], wh[2*i+1]); d[i] = __hsub2(wh[2*i], wh[2*i+1]); }
#pragma unroll
    for (int q = 0; q < 4; q++) { t[q] = __hadd2(s[2*q], s[2*q+1]); u[q] = __hsub2(s[2*q], s[2*q+1]); }
#pragma unroll
    for (int q = 0; q < 4; q++) o.Ah[q] = t[q];
    o.Bh[0] = __hadd2(u[0], u[1]); o.Bh[1] = __hadd2(u[2], u[3]);
    o.Dh[0] = __hsub2(t[0], t[1]); o.Dh[1] = __hsub2(t[2], t[3]);
    o.G2[0] = __hsub2(u[0], u[1]); o.G2[1] = __hsub2(u[2], u[3]);
    o.Eh = __hsub2(o.Bh[0], o.Bh[1]);
#pragma unroll
    for (int q = 0; q < 4; q++) { c[q] = __hadd2(d[2*q], d[2*q+1]); o.Ch[q] = c[q]; o.G4[q] = __hsub2(d[2*q], d[2*q+1]); }
    o.Fh[0] = __hsub2(c[0], c[1]); o.Fh[1] = __hsub2(c[2], c[3]);
    return o;
}

__device__ __forceinline__ void zero16h(__half2 w[16]) {
    const __half2 z = __float2half2_rn(0.0f);
#pragma unroll
    for (int m = 0; m < 16; m++) w[m] = z;
}

// ---- pair-packed half2 smem:  idx(c,pp) = (c>>1)*64 + 2*pp + (c&1) ----
__device__ __forceinline__ void load_chunkH(const __half2* __restrict__ s, int chunk,
                                            int pp, __half2 w[16]) {
#pragma unroll
    for (int i = 0; i < 8; i++) {
        uint2 r = *(const uint2*)(s + (8 * chunk + i) * 64 + 2 * pp);
        w[2*i]   = *(__half2*)&r.x;
        w[2*i+1] = *(__half2*)&r.y;
    }
}
__device__ __forceinline__ void sts_pair(__half2* __restrict__ s, int c, int pp,
                                         __half2 a, __half2 b) {   // c even
    uint2 r; r.x = *(unsigned*)&a; r.y = *(unsigned*)&b;
    *(uint2*)(s + (c >> 1) * 64 + 2 * pp) = r;
}
__device__ __forceinline__ void sts_one(__half2* __restrict__ s, int c, int pp,
                                        __half2 v) {
    s[(c >> 1) * 64 + 2 * pp + (c & 1)] = v;
}

__device__ __forceinline__ void store_GH(__half2* __restrict__ s, int jl, int pp,
                                         const GH& o, bool skipAl, bool skipH4) {
    const int jh = jl + 16;
    if (!skipAl) {                         // dead chunks 1,3 when skipped
        sts_pair(s, 4*jl,     pp, o.Al[0], o.Al[1]);
        sts_pair(s, 4*jl + 2, pp, o.Al[2], o.Al[3]);
    }
    sts_pair(s, 128 + 2*jl, pp, o.Bl[0], o.Bl[1]);
    sts_pair(s, 256 + 2*jl, pp, o.Dl[0], o.Dl[1]);
    sts_pair(s, 384 + 2*jl, pp, o.Gl[0], o.Gl[1]);
    sts_one (s, 320 + jl,   pp, o.El);
    if (!skipH4) {                         // dead chunks 7,15,31
        sts_pair(s, 4*jh,           pp, o.Ah[0], o.Ah[1]);
        sts_pair(s, 4*jh + 2,       pp, o.Ah[2], o.Ah[3]);
        sts_pair(s, 128 + 4*jh,     pp, o.Ch[0], o.Ch[1]);
        sts_pair(s, 128 + 4*jh + 2, pp, o.Ch[2], o.Ch[3]);
        sts_pair(s, 384 + 4*jh,     pp, o.G4[0], o.G4[1]);
        sts_pair(s, 384 + 4*jh + 2, pp, o.G4[2], o.G4[3]);
    }
    sts_pair(s, 128 + 2*jh, pp, o.Bh[0], o.Bh[1]);
    sts_pair(s, 256 + 2*jh, pp, o.Dh[0], o.Dh[1]);
    sts_pair(s, 384 + 2*jh, pp, o.G2[0], o.G2[1]);
    sts_pair(s, 320 + 2*jh, pp, o.Fh[0], o.Fh[1]);
    sts_one (s, 320 + jh,   pp, o.Eh);
}

// widen half2 (2 pixels of one channel) and store as float2
__device__ __forceinline__ void stg2(float* __restrict__ base, int ch, __half2 v) {
    *(float2*)(base + (size_t)ch * 784) = __half22float2(v);
}

__global__ __launch_bounds__(512, 2)
void dwht_kernel(const float* __restrict__ x, float* __restrict__ out) {
    extern __shared__ __half2 s[];     // 256 rows x 64 half2 = 64 KB

    const int tid = threadIdx.x;
    const int pp  = tid & (NPP - 1);   // pixel-pair lane within warp [0,32)
    const int jl  = tid >> 5;          // chunk pair id = warp id [0,16)
    const int jh  = jl + 16;

    const int b   = blockIdx.x / 13;
    const int pr  = (blockIdx.x % 13) * NPP + pp;   // pair index in image
    const bool valid = (pr < PAIRS_PER_IMG);
    const int hw0 = 2 * pr;
    const float* xp = x   + (size_t)b * (256 * 784) + hw0;
    float*       op = out + (size_t)b * (512 * 784) + hw0;

    // ---- stage 1: LDG.64 over pixel pair; fp32 compute; quantize once ----
    {
        float w0[16], w1[16];
#pragma unroll
        for (int m = 0; m < 16; m++) {
            float2 v = valid ? *(const float2*)(xp + (16 * jl + m) * 784)
                             : make_float2(0.f, 0.f);
            w0[m] = v.x; w1[m] = v.y;
        }
        LowF a = lowG_f(w0), c = lowG_f(w1);   // high outputs are exact zeros
        sts_pair(s, 4*jl,     pp, __floats2half2_rn(a.Al[0], c.Al[0]),
                                  __floats2half2_rn(a.Al[1], c.Al[1]));
        sts_pair(s, 4*jl + 2, pp, __floats2half2_rn(a.Al[2], c.Al[2]),
                                  __floats2half2_rn(a.Al[3], c.Al[3]));
        sts_pair(s, 128 + 2*jl, pp, __floats2half2_rn(a.Bl[0], c.Bl[0]),
                                    __floats2half2_rn(a.Bl[1], c.Bl[1]));
        sts_pair(s, 256 + 2*jl, pp, __floats2half2_rn(a.Dl[0], c.Dl[0]),
                                    __floats2half2_rn(a.Dl[1], c.Dl[1]));
        sts_pair(s, 384 + 2*jl, pp, __floats2half2_rn(a.Gl[0], c.Gl[0]),
                                    __floats2half2_rn(a.Gl[1], c.Gl[1]));
        sts_one (s, 320 + jl, pp, __floats2half2_rn(a.El, c.El));
    }
    __syncthreads();

    __half2 wl[16], wh[16];

    // ---- stage 2: nonzero input chunks {0,1,2,3,8,9,16,17,20,24,25} ----
    {
        const bool rl = (jl <= 3) | (jl == 8) | (jl == 9);
        const bool rh = (jl <= 1) | (jl == 4) | (jl == 8) | (jl == 9);
        if (rl) load_chunkH(s, jl, pp, wl); else zero16h(wl);
        if (rh) load_chunkH(s, jh, pp, wh); else zero16h(wh);
        GH o = compute_GH(wl, wh);
        __syncthreads();                  // all reads done before overwrite
        // outputs landing in chunks {1,3,7,15,31} are exact zeros: skip stores
        const bool skipAl = ((jl >= 4) & (jl <= 7)) | (jl >= 12);
        const bool skipH4 = (jl >= 12);
        store_GH(s, jl, pp, o, skipAl, skipH4);
        __syncthreads();
    }

    // ---- stage 3: chunks {1,3,7,15,31} are identically zero: skip reads ----
    {
        const bool rl = !((jl == 1) | (jl == 3) | (jl == 7) | (jl == 15));
        const bool rh = (jl != 15);
        if (rl) load_chunkH(s, jl, pp, wl); else zero16h(wl);
        if (rh) load_chunkH(s, jh, pp, wh); else zero16h(wh);
        GH o = compute_GH(wl, wh);
        __syncthreads();
        store_GH(s, jl, pp, o, false, false);
        __syncthreads();
    }

    // ---- stage 4: smem -> widen -> shuffled global STG.64 (affine) ----
    {
        load_chunkH(s, jl, pp, wl);
        load_chunkH(s, jh, pp, wh);
        GH o = compute_GH(wl, wh);
        if (valid) {
            // Shuffle c=((idx&63)<<3)|(idx>>6) solved per family:
            //   A:32jl+8q  Ah:+1  Ch:+3  G4:+7      (base q32)
            //   Bl/Dl/Gl: 16jl+8r+{2,4,6}           (base q16)
            //   Bh/Dh/Fh/G2: 256+16jl+8r+{2,4,5,6}  (base q16h)
            //   El: 8jl+5   Eh: 8jl+133             (base qE)
            float* q32  = op + (size_t)(32 * jl) * 784;
            float* q16  = op + (size_t)(16 * jl) * 784;
            float* q16h = q16 + (size_t)256 * 784;
            float* qE   = op + (size_t)(8 * jl) * 784;
#pragma unroll
            for (int q = 0; q < 4; q++) {
                stg2(q32, q*8 + 0, o.Al[q]);
                stg2(q32, q*8 + 1, o.Ah[q]);
                stg2(q32, q*8 + 3, o.Ch[q]);
                stg2(q32, q*8 + 7, o.G4[q]);
            }
#pragma unroll
            for (int r = 0; r < 2; r++) {
                stg2(q16,  r*8 + 2, o.Bl[r]);
                stg2(q16,  r*8 + 4, o.Dl[r]);
                stg2(q16,  r*8 + 6, o.Gl[r]);
                stg2(q16h, r*8 + 2, o.Bh[r]);
                stg2(q16h, r*8 + 4, o.Dh[r]);
                stg2(q16h, r*8 + 5, o.Fh[r]);
                stg2(q16h, r*8 + 6, o.G2[r]);
            }
            stg2(qE,   5, o.El);
            stg2(qE, 133, o.Eh);
        }
    }
}

extern "C" void kernel_launch(void* const* d_in, const int* in_sizes, int n_in,
                              void* d_out, int out_size) {
    const float* x = (const float*)d_in[0];
    float* out = (float*)d_out;
    const int smem = 256 * 64 * sizeof(__half2);   // 64 KB
    static bool attr_set = false;                  // idempotent host-side attr
    if (!attr_set) {
        cudaFuncSetAttribute(dwht_kernel,
                             cudaFuncAttributeMaxDynamicSharedMemorySize, smem);
        attr_set = true;
    }
    // 64 images * 13 tiles of 32 pixel-pairs (392 = 12*32 + 8; last predicated)
    dwht_kernel<<<64 * 13, 512, smem>>>(x, out);
}